// round 5
// baseline (speedup 1.0000x reference)
#include <cuda_runtime.h>
#include <math.h>
#include <cstdint>

// Problem dims
#define BV 32000
#define EMB 256
#define DU 512
#define BB 32
#define TIN 64
#define TOUT 64
#define BT (BB*TOUT)          // 2048
#define KIN (DU+EMB)          // 768

#define N_LOGITS  (BT*BV)
#define N_H       (BB*DU)

// ------------------------- scratch (static device globals) -------------------
__device__ float g_x[BT*EMB];           // embedded tokens   [2048,256]
__device__ float g_q[BT*DU];            // luong query       [2048,512]
__device__ float g_att[BT*DU];          // attention context [2048,512]
__device__ float g_lstmin[BT*KIN];      // concat(att,x)     [2048,768]
__device__ float g_zin[BT*4*DU];        // lstm_in@Wx + b    [2048,2048]
__device__ float g_hs[BT*DU];           // hidden states     [b,t,512]
__device__ unsigned g_bar;

// ------------------------- tiny kernels --------------------------------------
__global__ void zero_bar_kernel() { g_bar = 0u; }

__global__ void gather_x_kernel(const int* __restrict__ inp,
                                const float* __restrict__ emb) {
    int i = blockIdx.x * blockDim.x + threadIdx.x;
    if (i >= BT*EMB) return;
    int bt = i >> 8, e = i & 255;
    g_x[i] = emb[(size_t)inp[bt] * EMB + e];
}

__global__ void build_lstmin_kernel() {
    int i = blockIdx.x * blockDim.x + threadIdx.x;   // over 2048*768
    if (i >= BT*KIN) return;
    int bt = i / KIN, j = i % KIN;
    g_lstmin[i] = (j < DU) ? g_att[bt*DU + j] : g_x[bt*EMB + (j-DU)];
}

// ------------------------- packed fp32x2 SGEMM -------------------------------
// C[M,N] = A[M,K] @ B[K,N] + bias.  BM=BN=128, BK=16, 256 threads, 8x8/thread.
// Accumulators are 32 packed f32x2 (adjacent column pairs). A is staged in smem
// duplicated ({a,a} pairs) so the inner loop is pure ld.shared.v2.b64 +
// fma.rn.f32x2 (Blackwell FFMA2, 2x fp32 throughput).
typedef unsigned long long u64;

__device__ __forceinline__ void fma2(u64& c, u64 a, u64 b) {
    asm("fma.rn.f32x2 %0, %1, %2, %0;" : "+l"(c) : "l"(a), "l"(b));
}
__device__ __forceinline__ void lds_v2u64(u64& x, u64& y, const void* p) {
    asm volatile("ld.shared.v2.b64 {%0,%1}, [%2];"
                 : "=l"(x), "=l"(y)
                 : "l"(__cvta_generic_to_shared(p)));
}

__global__ __launch_bounds__(256, 2)
void sgemm2_kernel(const float* __restrict__ A, const float* __restrict__ B,
                   const float* __restrict__ bias, float* __restrict__ C,
                   int M, int N, int K) {
    __shared__ float As[2][16][256];   // [buf][kk][2*row] duplicated pairs
    __shared__ float Bs[2][16][128];   // [buf][kk][col]

    const int tid = threadIdx.x;
    const int tx = tid & 15, ty = tid >> 4;          // 16 x 16 thread grid
    const int row0 = blockIdx.y * 128, col0 = blockIdx.x * 128;

    u64 acc[8][4];
#pragma unroll
    for (int i = 0; i < 8; i++)
#pragma unroll
        for (int j = 0; j < 4; j++) acc[i][j] = 0ull;

    // global-load thread mapping
    const int ar = tid >> 2, aq = tid & 3;           // A: row, k-float4
    const int bk = tid >> 5, bc = tid & 31;          // B: k-row, n-float4

    const int nch = K >> 4;
    float4 a0, a1, b0, b1;

    // prologue: chunk 0 -> regs -> smem buf0
    {
        a0 = *(const float4*)&A[(size_t)(row0 + ar) * K + aq*4];
        a1 = *(const float4*)&A[(size_t)(row0 + ar + 64) * K + aq*4];
        b0 = *(const float4*)&B[(size_t)bk * N + col0 + bc*4];
        b1 = *(const float4*)&B[(size_t)(bk + 8) * N + col0 + bc*4];
        float av0[4] = {a0.x, a0.y, a0.z, a0.w};
        float av1[4] = {a1.x, a1.y, a1.z, a1.w};
#pragma unroll
        for (int c = 0; c < 4; c++) {
            ((float2*)&As[0][aq*4 + c][0])[ar]      = make_float2(av0[c], av0[c]);
            ((float2*)&As[0][aq*4 + c][0])[ar + 64] = make_float2(av1[c], av1[c]);
        }
        *(float4*)&Bs[0][bk][bc*4]     = b0;
        *(float4*)&Bs[0][bk + 8][bc*4] = b1;
    }
    __syncthreads();

    for (int ch = 0; ch < nch; ch++) {
        const int cur = ch & 1;
        const bool more = (ch + 1) < nch;
        if (more) {
            const int k0 = (ch + 1) << 4;
            a0 = *(const float4*)&A[(size_t)(row0 + ar) * K + k0 + aq*4];
            a1 = *(const float4*)&A[(size_t)(row0 + ar + 64) * K + k0 + aq*4];
            b0 = *(const float4*)&B[(size_t)(k0 + bk) * N + col0 + bc*4];
            b1 = *(const float4*)&B[(size_t)(k0 + bk + 8) * N + col0 + bc*4];
        }

#pragma unroll
        for (int kk = 0; kk < 16; kk++) {
            u64 ap[8], bp[4];
            lds_v2u64(ap[0], ap[1], &As[cur][kk][ty*16 + 0]);
            lds_v2u64(ap[2], ap[3], &As[cur][kk][ty*16 + 4]);
            lds_v2u64(ap[4], ap[5], &As[cur][kk][ty*16 + 8]);
            lds_v2u64(ap[6], ap[7], &As[cur][kk][ty*16 + 12]);
            lds_v2u64(bp[0], bp[1], &Bs[cur][kk][tx*8 + 0]);
            lds_v2u64(bp[2], bp[3], &Bs[cur][kk][tx*8 + 4]);
#pragma unroll
            for (int i = 0; i < 8; i++)
#pragma unroll
                for (int j = 0; j < 4; j++)
                    fma2(acc[i][j], ap[i], bp[j]);
        }
        __syncthreads();
        if (more) {
            const int nxt = cur ^ 1;
            float av0[4] = {a0.x, a0.y, a0.z, a0.w};
            float av1[4] = {a1.x, a1.y, a1.z, a1.w};
#pragma unroll
            for (int c = 0; c < 4; c++) {
                ((float2*)&As[nxt][aq*4 + c][0])[ar]      = make_float2(av0[c], av0[c]);
                ((float2*)&As[nxt][aq*4 + c][0])[ar + 64] = make_float2(av1[c], av1[c]);
            }
            *(float4*)&Bs[nxt][bk][bc*4]     = b0;
            *(float4*)&Bs[nxt][bk + 8][bc*4] = b1;
            __syncthreads();
        }
    }

    // epilogue: unpack pairs, add bias, store 8 rows x 8 cols
    const int cc = col0 + tx*8;
    float4 bias_lo = *(const float4*)&bias[cc];
    float4 bias_hi = *(const float4*)&bias[cc + 4];
#pragma unroll
    for (int i = 0; i < 8; i++) {
        const size_t r = (size_t)(row0 + ty*8 + i);
        float2 p0 = *(float2*)&acc[i][0];
        float2 p1 = *(float2*)&acc[i][1];
        float2 p2 = *(float2*)&acc[i][2];
        float2 p3 = *(float2*)&acc[i][3];
        float4 v0 = make_float4(p0.x + bias_lo.x, p0.y + bias_lo.y,
                                p1.x + bias_lo.z, p1.y + bias_lo.w);
        float4 v1 = make_float4(p2.x + bias_hi.x, p2.y + bias_hi.y,
                                p3.x + bias_hi.z, p3.y + bias_hi.w);
        *(float4*)&C[r * N + cc]     = v0;
        *(float4*)&C[r * N + cc + 4] = v1;
    }
}

// ------------------------- attention (one block per (b,t)) -------------------
__global__ __launch_bounds__(256)
void attn_kernel(const float* __restrict__ enc, float* __restrict__ attn_out) {
    int bt = blockIdx.x;
    int b = bt >> 6;
    __shared__ float sq[DU];
    __shared__ float sc[TIN];
    __shared__ float red[2];
    int tid = threadIdx.x;
    int w = tid >> 5, lane = tid & 31;

    for (int i = tid; i < DU; i += 256) sq[i] = g_q[(size_t)bt*DU + i];
    __syncthreads();

    const float* encb = enc + (size_t)b * TIN * DU;
    for (int s = w; s < TIN; s += 8) {
        const float* e = encb + (size_t)s * DU;
        float sum = 0.f;
        for (int d = lane; d < DU; d += 32) sum += sq[d] * e[d];
#pragma unroll
        for (int o = 16; o > 0; o >>= 1) sum += __shfl_xor_sync(0xffffffffu, sum, o);
        if (lane == 0) sc[s] = sum;
    }
    __syncthreads();

    if (w == 0) {
        float v = fmaxf(sc[lane], sc[lane + 32]);
#pragma unroll
        for (int o = 16; o > 0; o >>= 1) v = fmaxf(v, __shfl_xor_sync(0xffffffffu, v, o));
        if (lane == 0) red[0] = v;
    }
    __syncthreads();
    float m = red[0];
    if (tid < TIN) sc[tid] = expf(sc[tid] - m);
    __syncthreads();
    if (w == 0) {
        float v = sc[lane] + sc[lane + 32];
#pragma unroll
        for (int o = 16; o > 0; o >>= 1) v += __shfl_xor_sync(0xffffffffu, v, o);
        if (lane == 0) red[1] = v;
    }
    __syncthreads();
    float inv = 1.f / red[1];
    if (tid < TIN) {
        float wv = sc[tid] * inv;
        sc[tid] = wv;
        attn_out[(size_t)bt * TIN + tid] = wv;
    }
    __syncthreads();

    for (int d = tid; d < DU; d += 256) {
        float sum = 0.f;
#pragma unroll 8
        for (int s = 0; s < TIN; s++) sum += sc[s] * encb[(size_t)s * DU + d];
        g_att[(size_t)bt * DU + d] = sum;
    }
}

// ------------------------- persistent LSTM recurrence ------------------------
__global__ __launch_bounds__(128)
void lstm_kernel(const float* __restrict__ Wh,
                 const float* __restrict__ h0,
                 const float* __restrict__ c0,
                 float* __restrict__ out_h,
                 float* __restrict__ out_c) {
    extern __shared__ float smemf[];
    float* sh = smemf;                     // [512][32] h transposed
    float* zx = smemf + DU*BB;             // [4 gate][4 dl][32 b]

    const int tid = threadIdx.x;
    const int b = tid & 31, q = tid >> 5;
    const int d0 = blockIdx.x * 4;
    const unsigned nblk = gridDim.x;

    float c = c0[(size_t)b*DU + d0 + q];
    float hlast = 0.f;

    for (int t = 0; t < TOUT; t++) {
        if (t == 0) {
            for (int i = tid; i < BB*DU; i += 128) {
                int bb = i >> 9, k = i & 511;
                sh[k*32 + bb] = __ldcg(&h0[i]);
            }
        } else {
            for (int i = tid; i < BB*DU; i += 128) {
                int bb = i >> 9, k = i & 511;
                sh[k*32 + bb] = __ldcg(&g_hs[((size_t)bb*TOUT + (t-1))*DU + k]);
            }
        }
        __syncthreads();

        const float4* wp = (const float4*)(Wh + q*DU + d0);
        float4 z = *(const float4*)(&g_zin[((size_t)b*TOUT + t)*(4*DU) + q*DU + d0]);
        float a0 = z.x, a1 = z.y, a2 = z.z, a3 = z.w;
#pragma unroll 8
        for (int k = 0; k < DU; k++) {
            float hv = sh[k*32 + b];
            float4 wv = wp[(size_t)k * 512];
            a0 += hv * wv.x; a1 += hv * wv.y; a2 += hv * wv.z; a3 += hv * wv.w;
        }
        zx[(q*4 + 0)*32 + b] = a0;
        zx[(q*4 + 1)*32 + b] = a1;
        zx[(q*4 + 2)*32 + b] = a2;
        zx[(q*4 + 3)*32 + b] = a3;
        __syncthreads();

        float zi = zx[(0*4 + q)*32 + b];
        float zf = zx[(1*4 + q)*32 + b];
        float zg = zx[(2*4 + q)*32 + b];
        float zo = zx[(3*4 + q)*32 + b];
        float fi = 1.f / (1.f + expf(-zi));
        float ff = 1.f / (1.f + expf(-zf));
        float gg = tanhf(zg);
        float oo = 1.f / (1.f + expf(-zo));
        c = ff * c + fi * gg;
        float h = oo * tanhf(c);
        hlast = h;
        g_hs[((size_t)b*TOUT + t)*DU + d0 + q] = h;
        __syncthreads();

        if (tid == 0) {
            __threadfence();
            atomicAdd(&g_bar, 1u);
            unsigned target = (unsigned)(t + 1) * nblk;
            while (*((volatile unsigned*)&g_bar) < target) { }
        }
        __syncthreads();
    }

    out_c[(size_t)b*DU + d0 + q] = c;
    out_h[(size_t)b*DU + d0 + q] = hlast;
}

// ------------------------- host launcher -------------------------------------
extern "C" void kernel_launch(void* const* d_in, const int* in_sizes, int n_in,
                              void* d_out, int out_size) {
    const int*   inputs = (const int*)  d_in[0];
    const float* enc    = (const float*)d_in[1];
    const float* h0     = (const float*)d_in[2];
    const float* c0     = (const float*)d_in[3];
    const float* emb    = (const float*)d_in[4];
    const float* Wq     = (const float*)d_in[5];
    const float* bq     = (const float*)d_in[6];
    const float* Wx     = (const float*)d_in[7];
    const float* Wh     = (const float*)d_in[8];
    const float* b_lstm = (const float*)d_in[9];
    const float* Wfc    = (const float*)d_in[10];
    const float* bfc    = (const float*)d_in[11];

    float* out        = (float*)d_out;
    float* out_logits = out;
    float* out_h      = out + (size_t)N_LOGITS;
    float* out_c      = out_h + N_H;
    float* out_attn   = out_c + N_H;

    float *px, *pq, *pin, *pzin, *phs;
    cudaGetSymbolAddress((void**)&px,   g_x);
    cudaGetSymbolAddress((void**)&pq,   g_q);
    cudaGetSymbolAddress((void**)&pin,  g_lstmin);
    cudaGetSymbolAddress((void**)&pzin, g_zin);
    cudaGetSymbolAddress((void**)&phs,  g_hs);

    int lstm_smem = (DU*BB + 4*4*BB) * (int)sizeof(float);
    cudaFuncSetAttribute(lstm_kernel,
                         cudaFuncAttributeMaxDynamicSharedMemorySize, lstm_smem);

    zero_bar_kernel<<<1, 1>>>();

    gather_x_kernel<<<(BT*EMB + 255)/256, 256>>>(inputs, emb);

    // q = x @ Wq + bq      [2048,256]@[256,512]
    sgemm2_kernel<<<dim3(DU/128, BT/128), 256>>>(px, Wq, bq, pq, BT, DU, EMB);

    attn_kernel<<<BT, 256>>>(enc, out_attn);

    build_lstmin_kernel<<<(BT*KIN + 255)/256, 256>>>();

    // Z_in = lstm_in @ Wx + b_lstm   [2048,768]@[768,2048]
    sgemm2_kernel<<<dim3((4*DU)/128, BT/128), 256>>>(pin, Wx, b_lstm, pzin,
                                                     BT, 4*DU, KIN);

    lstm_kernel<<<128, 128, lstm_smem>>>(Wh, h0, c0, out_h, out_c);

    // logits = hs @ Wfc + bfc   [2048,512]@[512,32000]
    sgemm2_kernel<<<dim3(BV/128, BT/128), 256>>>(phs, Wfc, bfc, out_logits,
                                                 BT, BV, DU);
}

// round 6
// speedup vs baseline: 3.9370x; 3.9370x over previous
#include <cuda_runtime.h>
#include <cuda_bf16.h>
#include <math.h>
#include <cstdint>

// Problem dims
#define BV 32000
#define EMB 256
#define DU 512
#define BB 32
#define TIN 64
#define TOUT 64
#define BT (BB*TOUT)          // 2048
#define KIN (DU+EMB)          // 768

#define N_LOGITS  (BT*BV)
#define N_H       (BB*DU)

// ------------------------- scratch (static device globals) -------------------
__device__ float g_x[BT*EMB];           // embedded tokens   [2048,256]
__device__ float g_q[BT*DU];            // luong query       [2048,512]
__device__ float g_att[BT*DU];          // attention context [2048,512]
__device__ float g_zin[BT*4*DU];        // lstm_in@Wx + b    [2048,2048]
__device__ float g_hs[BT*DU];           // hidden states fp32 (staging)
__device__ float g_WhP[128*512*16];     // Wh packed per LSTM block (4 MB)
__device__ unsigned g_bar;

// bf16 split operands (16B-aligned for cp.async / uint4)
__device__ __align__(16) __nv_bfloat16 g_lin_h[BT*KIN],  g_lin_l[BT*KIN];
__device__ __align__(16) __nv_bfloat16 g_Wx_h[KIN*4*DU], g_Wx_l[KIN*4*DU];
__device__ __align__(16) __nv_bfloat16 g_hs_h[BT*DU],    g_hs_l[BT*DU];
__device__ __align__(16) __nv_bfloat16 g_Wfc_h[(size_t)DU*BV], g_Wfc_l[(size_t)DU*BV];

// ------------------------- tiny kernels --------------------------------------
__global__ void zero_bar_kernel() { g_bar = 0u; }

__global__ void gather_x_kernel(const int* __restrict__ inp,
                                const float* __restrict__ emb) {
    int i = blockIdx.x * blockDim.x + threadIdx.x;
    if (i >= BT*EMB) return;
    int bt = i >> 8, e = i & 255;
    g_x[i] = emb[(size_t)inp[bt] * EMB + e];
}

__device__ __forceinline__ void split_store(float v, __nv_bfloat16* hi,
                                            __nv_bfloat16* lo, size_t i) {
    __nv_bfloat16 h = __float2bfloat16(v);
    hi[i] = h;
    lo[i] = __float2bfloat16(v - __bfloat162float(h));
}

__global__ void split_kernel(const float* __restrict__ in,
                             __nv_bfloat16* __restrict__ hi,
                             __nv_bfloat16* __restrict__ lo, int n) {
    int i = blockIdx.x * blockDim.x + threadIdx.x;
    if (i >= n) return;
    split_store(in[i], hi, lo, i);
}

__global__ void build_lstmin_split_kernel() {
    int i = blockIdx.x * blockDim.x + threadIdx.x;   // over 2048*768
    if (i >= BT*KIN) return;
    int bt = i / KIN, j = i % KIN;
    float v = (j < DU) ? g_att[bt*DU + j] : g_x[bt*EMB + (j-DU)];
    split_store(v, g_lin_h, g_lin_l, i);
}

// Pack Wh[512, 2048] into per-block slices: g_WhP[blk][k][q][j] = Wh[k][q*512 + blk*4 + j]
__global__ void pack_wh_kernel(const float* __restrict__ Wh) {
    int i = blockIdx.x * blockDim.x + threadIdx.x;   // over 128*512*16
    if (i >= 128*512*16) return;
    int blk = i >> 13;
    int rem = i & 8191;
    int k = rem >> 4, t = rem & 15;
    int q = t >> 2, j = t & 3;
    g_WhP[i] = Wh[(size_t)k*2048 + q*512 + blk*4 + j];
}

// ------------------------- scalar fp32 SGEMM (small q GEMM only) -------------
__global__ __launch_bounds__(256)
void sgemm_kernel(const float* __restrict__ A, const float* __restrict__ B,
                  const float* __restrict__ bias, float* __restrict__ C,
                  int M, int N, int K) {
    __shared__ float As[8][128];
    __shared__ float Bs[8][128];
    const int tid = threadIdx.x;
    const int tx = tid & 15, ty = tid >> 4;
    const int row0 = blockIdx.y * 128, col0 = blockIdx.x * 128;

    float acc[8][8];
#pragma unroll
    for (int i = 0; i < 8; i++)
#pragma unroll
        for (int j = 0; j < 8; j++) acc[i][j] = 0.f;

    for (int k0 = 0; k0 < K; k0 += 8) {
#pragma unroll
        for (int l = 0; l < 4; l++) {
            int idx = tid + l*256;
            int r = idx >> 3, kk = idx & 7;
            As[kk][r] = A[(size_t)(row0 + r) * K + k0 + kk];
        }
#pragma unroll
        for (int l = 0; l < 4; l++) {
            int idx = tid + l*256;
            int kk = idx >> 7, c = idx & 127;
            Bs[kk][c] = B[(size_t)(k0 + kk) * N + col0 + c];
        }
        __syncthreads();
#pragma unroll
        for (int kk = 0; kk < 8; kk++) {
            float a[8], b[8];
#pragma unroll
            for (int i = 0; i < 8; i++) a[i] = As[kk][ty*8 + i];
#pragma unroll
            for (int j = 0; j < 8; j++) b[j] = Bs[kk][tx*8 + j];
#pragma unroll
            for (int i = 0; i < 8; i++)
#pragma unroll
                for (int j = 0; j < 8; j++) acc[i][j] += a[i] * b[j];
        }
        __syncthreads();
    }
#pragma unroll
    for (int i = 0; i < 8; i++) {
        size_t r = row0 + ty*8 + i;
#pragma unroll
        for (int j = 0; j < 8; j++) {
            int cc = col0 + tx*8 + j;
            C[r * N + cc] = acc[i][j] + bias[cc];
        }
    }
}

// ------------------------- pipelined bf16x3 mma GEMM -------------------------
// C[M,N] = A[M,K]@B[K,N] + bias; A,B as (hi,lo) bf16. CTA 128x128, BK=32,
// 8 warps (2M x 4N, warp 64x32), mma.m16n8k16 x3 precision passes.
// 3-stage cp.async.cg pipeline; padded smem (A stride 40, B stride 136 bf16).
#define BKC 32
#define NSTG 3
#define OFF_AL_B 10240
#define OFF_BH_B 20480
#define OFF_BL_B 29184
#define STAGE_B  37888
#define GEMM_SMEM (NSTG*STAGE_B)

__device__ __forceinline__ uint32_t smem_u32(const void* p) {
    return (uint32_t)__cvta_generic_to_shared(p);
}
__device__ __forceinline__ void cp16(void* dst, const void* src) {
    uint32_t d = smem_u32(dst);
    asm volatile("cp.async.cg.shared.global [%0], [%1], 16;"
                 :: "r"(d), "l"(src) : "memory");
}
__device__ __forceinline__ void cp_commit() {
    asm volatile("cp.async.commit_group;" ::: "memory");
}
__device__ __forceinline__ void cp_wait1() {
    asm volatile("cp.async.wait_group 1;" ::: "memory");
}
__device__ __forceinline__ void ldsm_x4(unsigned* r, uint32_t addr) {
    asm volatile("ldmatrix.sync.aligned.m8n8.x4.shared.b16 {%0,%1,%2,%3}, [%4];"
                 : "=r"(r[0]), "=r"(r[1]), "=r"(r[2]), "=r"(r[3]) : "r"(addr));
}
__device__ __forceinline__ void ldsm_x4_t(unsigned* r, uint32_t addr) {
    asm volatile("ldmatrix.sync.aligned.m8n8.x4.trans.shared.b16 {%0,%1,%2,%3}, [%4];"
                 : "=r"(r[0]), "=r"(r[1]), "=r"(r[2]), "=r"(r[3]) : "r"(addr));
}
__device__ __forceinline__ void mma16816(float* c, const unsigned* a,
                                         unsigned b0, unsigned b1) {
    asm volatile(
        "mma.sync.aligned.m16n8k16.row.col.f32.bf16.bf16.f32 "
        "{%0,%1,%2,%3}, {%4,%5,%6,%7}, {%8,%9}, {%0,%1,%2,%3};"
        : "+f"(c[0]), "+f"(c[1]), "+f"(c[2]), "+f"(c[3])
        : "r"(a[0]), "r"(a[1]), "r"(a[2]), "r"(a[3]), "r"(b0), "r"(b1));
}

__device__ __forceinline__ void gemm_issue(
        const __nv_bfloat16* Ah, const __nv_bfloat16* Al,
        const __nv_bfloat16* Bh, const __nv_bfloat16* Bl,
        char* smc, int ch, int tid, int row0, int col0, int K, int N) {
    char* sb = smc + (ch % NSTG) * STAGE_B;
    const int k0 = ch * BKC;
#pragma unroll
    for (int l = 0; l < 2; l++) {
        int c = tid*2 + l;                 // 0..511
        int r = c >> 2, q = c & 3;         // A: 128 rows x 4 chunks (64B row)
        size_t g = (size_t)(row0 + r) * K + k0 + q*8;
        cp16(sb + r*80 + q*16, Ah + g);
        cp16(sb + OFF_AL_B + r*80 + q*16, Al + g);
    }
#pragma unroll
    for (int l = 0; l < 2; l++) {
        int c = tid*2 + l;
        int r = c >> 4, q = c & 15;        // B: 32 rows x 16 chunks (256B row)
        size_t g = (size_t)(k0 + r) * N + col0 + q*8;
        cp16(sb + OFF_BH_B + r*272 + q*16, Bh + g);
        cp16(sb + OFF_BL_B + r*272 + q*16, Bl + g);
    }
    cp_commit();
}

__global__ __launch_bounds__(256)
void gemm_mma3_kernel(const __nv_bfloat16* __restrict__ Ah,
                      const __nv_bfloat16* __restrict__ Al,
                      const __nv_bfloat16* __restrict__ Bh,
                      const __nv_bfloat16* __restrict__ Bl,
                      const float* __restrict__ bias,
                      float* __restrict__ C,
                      int M, int N, int K) {
    extern __shared__ char smc[];
    const uint32_t sbase = smem_u32(smc);
    const int tid  = threadIdx.x;
    const int lane = tid & 31;
    const int warp = tid >> 5;
    const int wm = warp & 1;
    const int wn = warp >> 1;
    const int row0 = blockIdx.y * 128;
    const int col0 = blockIdx.x * 128;

    float acc[4][4][4];
#pragma unroll
    for (int i = 0; i < 4; i++)
#pragma unroll
        for (int j = 0; j < 4; j++)
#pragma unroll
            for (int r = 0; r < 4; r++) acc[i][j][r] = 0.f;

    const int grp = lane >> 3;
    const unsigned a_row  = (lane & 15);
    const unsigned a_koff = (lane >> 4) << 3;
    const unsigned b_row  = ((grp & 1) << 3) + (lane & 7);
    const unsigned b_coff = wn*32 + ((grp >> 1) << 3);

    const int nch = K / BKC;
    gemm_issue(Ah, Al, Bh, Bl, smc, 0, tid, row0, col0, K, N);
    gemm_issue(Ah, Al, Bh, Bl, smc, 1, tid, row0, col0, K, N);

    for (int ch = 0; ch < nch; ch++) {
        cp_wait1();
        __syncthreads();
        if (ch + 2 < nch)
            gemm_issue(Ah, Al, Bh, Bl, smc, ch + 2, tid, row0, col0, K, N);
        else
            cp_commit();                    // keep group count moving

        const uint32_t st = sbase + (ch % NSTG) * STAGE_B;
        const uint32_t aH = st, aL = st + OFF_AL_B;
        const uint32_t bH = st + OFF_BH_B, bL = st + OFF_BL_B;
#pragma unroll
        for (int kk = 0; kk < BKC; kk += 16) {
            unsigned a_h[4][4], a_l[4][4], b_h[2][4], b_l[2][4];
#pragma unroll
            for (int mt = 0; mt < 4; mt++) {
                uint32_t off = ((wm*64 + mt*16 + a_row) * 40 + kk + a_koff) * 2;
                ldsm_x4(a_h[mt], aH + off);
                ldsm_x4(a_l[mt], aL + off);
            }
#pragma unroll
            for (int p = 0; p < 2; p++) {
                uint32_t off = ((kk + b_row) * 136 + b_coff + p*16) * 2;
                ldsm_x4_t(b_h[p], bH + off);
                ldsm_x4_t(b_l[p], bL + off);
            }
#pragma unroll
            for (int mt = 0; mt < 4; mt++)
#pragma unroll
                for (int p = 0; p < 2; p++)
#pragma unroll
                    for (int hf = 0; hf < 2; hf++) {
                        int nt = p*2 + hf;
                        unsigned bh0 = b_h[p][hf*2], bh1 = b_h[p][hf*2+1];
                        unsigned bl0 = b_l[p][hf*2], bl1 = b_l[p][hf*2+1];
                        mma16816(acc[mt][nt], a_h[mt], bh0, bh1);
                        mma16816(acc[mt][nt], a_h[mt], bl0, bl1);
                        mma16816(acc[mt][nt], a_l[mt], bh0, bh1);
                    }
        }
    }

    // epilogue: fp32 + bias
#pragma unroll
    for (int mt = 0; mt < 4; mt++) {
        int r_up = row0 + wm*64 + mt*16 + (lane >> 2);
        int r_dn = r_up + 8;
#pragma unroll
        for (int nt = 0; nt < 4; nt++) {
            int cc = col0 + wn*32 + nt*8 + (lane & 3)*2;
            float b0 = bias[cc], b1 = bias[cc+1];
            *(float2*)&C[(size_t)r_up * N + cc] =
                make_float2(acc[mt][nt][0] + b0, acc[mt][nt][1] + b1);
            *(float2*)&C[(size_t)r_dn * N + cc] =
                make_float2(acc[mt][nt][2] + b0, acc[mt][nt][3] + b1);
        }
    }
}

// ------------------------- attention (one block per (b,t)) -------------------
__global__ __launch_bounds__(256)
void attn_kernel(const float* __restrict__ enc, float* __restrict__ attn_out) {
    int bt = blockIdx.x;
    int b = bt >> 6;
    __shared__ float sq[DU];
    __shared__ float sc[TIN];
    __shared__ float red[2];
    int tid = threadIdx.x;
    int w = tid >> 5, lane = tid & 31;

    for (int i = tid; i < DU; i += 256) sq[i] = g_q[(size_t)bt*DU + i];
    __syncthreads();

    const float* encb = enc + (size_t)b * TIN * DU;
    for (int s = w; s < TIN; s += 8) {
        const float* e = encb + (size_t)s * DU;
        float sum = 0.f;
        for (int d = lane; d < DU; d += 32) sum += sq[d] * e[d];
#pragma unroll
        for (int o = 16; o > 0; o >>= 1) sum += __shfl_xor_sync(0xffffffffu, sum, o);
        if (lane == 0) sc[s] = sum;
    }
    __syncthreads();

    if (w == 0) {
        float v = fmaxf(sc[lane], sc[lane + 32]);
#pragma unroll
        for (int o = 16; o > 0; o >>= 1) v = fmaxf(v, __shfl_xor_sync(0xffffffffu, v, o));
        if (lane == 0) red[0] = v;
    }
    __syncthreads();
    float m = red[0];
    if (tid < TIN) sc[tid] = expf(sc[tid] - m);
    __syncthreads();
    if (w == 0) {
        float v = sc[lane] + sc[lane + 32];
#pragma unroll
        for (int o = 16; o > 0; o >>= 1) v += __shfl_xor_sync(0xffffffffu, v, o);
        if (lane == 0) red[1] = v;
    }
    __syncthreads();
    float inv = 1.f / red[1];
    if (tid < TIN) {
        float wv = sc[tid] * inv;
        sc[tid] = wv;
        attn_out[(size_t)bt * TIN + tid] = wv;
    }
    __syncthreads();

    for (int d = tid; d < DU; d += 256) {
        float sum = 0.f;
#pragma unroll 8
        for (int s = 0; s < TIN; s++) sum += sc[s] * encb[(size_t)s * DU + d];
        g_att[(size_t)bt * DU + d] = sum;
    }
}

// ------------------------- persistent LSTM recurrence ------------------------
// 128 blocks x 128 threads; block owns 4 d-cols x 4 gates. Wh slice (32 KB,
// packed by pack_wh_kernel) lives in smem for all 64 steps; h staged through
// L2 each step; c in a register. Writes fp32 hs + bf16 hi/lo splits.
#define LSTM_SMEM ((DU*BB + DU*16 + 4*4*BB) * 4)

__global__ __launch_bounds__(128)
void lstm_kernel(const float* __restrict__ h0,
                 const float* __restrict__ c0,
                 float* __restrict__ out_h,
                 float* __restrict__ out_c) {
    extern __shared__ float smemf[];
    float*  sh  = smemf;                    // [512][32] h transposed
    float4* sW4 = (float4*)(smemf + DU*BB); // [512][4 gates] packed Wh
    float*  zx  = smemf + DU*BB + DU*16;    // [4 gate][4 dl][32 b]

    const int tid = threadIdx.x;
    const int b = tid & 31, q = tid >> 5;
    const int d0 = blockIdx.x * 4;
    const unsigned nblk = gridDim.x;

    // load packed Wh slice once (32 KB, coalesced)
    {
        const float4* src = (const float4*)&g_WhP[(size_t)blockIdx.x * 8192];
        for (int i = tid; i < 2048; i += 128) sW4[i] = src[i];
    }

    float c = c0[(size_t)b*DU + d0 + q];
    float hlast = 0.f;

    for (int t = 0; t < TOUT; t++) {
        if (t == 0) {
            for (int i = tid; i < BB*DU; i += 128) {
                int bb = i >> 9, k = i & 511;
                sh[k*32 + bb] = __ldcg(&h0[i]);
            }
        } else {
            for (int i = tid; i < BB*DU; i += 128) {
                int bb = i >> 9, k = i & 511;
                sh[k*32 + bb] = __ldcg(&g_hs[((size_t)bb*TOUT + (t-1))*DU + k]);
            }
        }
        __syncthreads();

        float4 z = *(const float4*)(&g_zin[((size_t)b*TOUT + t)*(4*DU) + q*DU + d0]);
        float a0 = z.x, a1 = z.y, a2 = z.z, a3 = z.w;
#pragma unroll 8
        for (int k = 0; k < DU; k++) {
            float hv = sh[k*32 + b];
            float4 wv = sW4[k*4 + q];
            a0 += hv * wv.x; a1 += hv * wv.y; a2 += hv * wv.z; a3 += hv * wv.w;
        }
        zx[(q*4 + 0)*32 + b] = a0;
        zx[(q*4 + 1)*32 + b] = a1;
        zx[(q*4 + 2)*32 + b] = a2;
        zx[(q*4 + 3)*32 + b] = a3;
        __syncthreads();

        float zi = zx[(0*4 + q)*32 + b];
        float zf = zx[(1*4 + q)*32 + b];
        float zg = zx[(2*4 + q)*32 + b];
        float zo = zx[(3*4 + q)*32 + b];
        float fi = 1.f / (1.f + expf(-zi));
        float ff = 1.f / (1.f + expf(-zf));
        float gg = tanhf(zg);
        float oo = 1.f / (1.f + expf(-zo));
        c = ff * c + fi * gg;
        float h = oo * tanhf(c);
        hlast = h;
        const size_t oidx = ((size_t)b*TOUT + t)*DU + d0 + q;
        g_hs[oidx] = h;
        __nv_bfloat16 hh = __float2bfloat16(h);
        g_hs_h[oidx] = hh;
        g_hs_l[oidx] = __float2bfloat16(h - __bfloat162float(hh));
        __syncthreads();

        if (tid == 0) {
            __threadfence();
            atomicAdd(&g_bar, 1u);
            unsigned target = (unsigned)(t + 1) * nblk;
            while (*((volatile unsigned*)&g_bar) < target) { }
        }
        __syncthreads();
    }

    out_c[(size_t)b*DU + d0 + q] = c;
    out_h[(size_t)b*DU + d0 + q] = hlast;
}

// ------------------------- host launcher -------------------------------------
extern "C" void kernel_launch(void* const* d_in, const int* in_sizes, int n_in,
                              void* d_out, int out_size) {
    const int*   inputs = (const int*)  d_in[0];
    const float* enc    = (const float*)d_in[1];
    const float* h0     = (const float*)d_in[2];
    const float* c0     = (const float*)d_in[3];
    const float* emb    = (const float*)d_in[4];
    const float* Wq     = (const float*)d_in[5];
    const float* bq     = (const float*)d_in[6];
    const float* Wx     = (const float*)d_in[7];
    const float* Wh     = (const float*)d_in[8];
    const float* b_lstm = (const float*)d_in[9];
    const float* Wfc    = (const float*)d_in[10];
    const float* bfc    = (const float*)d_in[11];

    float* out        = (float*)d_out;
    float* out_logits = out;
    float* out_h      = out + (size_t)N_LOGITS;
    float* out_c      = out_h + N_H;
    float* out_attn   = out_c + N_H;

    float *px, *pq, *pzin;
    __nv_bfloat16 *plin_h, *plin_l, *pWx_h, *pWx_l, *phs_h, *phs_l, *pWfc_h, *pWfc_l;
    cudaGetSymbolAddress((void**)&px,   g_x);
    cudaGetSymbolAddress((void**)&pq,   g_q);
    cudaGetSymbolAddress((void**)&pzin, g_zin);
    cudaGetSymbolAddress((void**)&plin_h, g_lin_h);
    cudaGetSymbolAddress((void**)&plin_l, g_lin_l);
    cudaGetSymbolAddress((void**)&pWx_h,  g_Wx_h);
    cudaGetSymbolAddress((void**)&pWx_l,  g_Wx_l);
    cudaGetSymbolAddress((void**)&phs_h,  g_hs_h);
    cudaGetSymbolAddress((void**)&phs_l,  g_hs_l);
    cudaGetSymbolAddress((void**)&pWfc_h, g_Wfc_h);
    cudaGetSymbolAddress((void**)&pWfc_l, g_Wfc_l);

    cudaFuncSetAttribute(lstm_kernel,
                         cudaFuncAttributeMaxDynamicSharedMemorySize, LSTM_SMEM);
    cudaFuncSetAttribute(gemm_mma3_kernel,
                         cudaFuncAttributeMaxDynamicSharedMemorySize, GEMM_SMEM);

    zero_bar_kernel<<<1, 1>>>();

    gather_x_kernel<<<(BT*EMB + 255)/256, 256>>>(inputs, emb);

    // q = x @ Wq + bq  (small, fp32)
    sgemm_kernel<<<dim3(DU/128, BT/128), 256>>>(px, Wq, bq, pq, BT, DU, EMB);

    attn_kernel<<<BT, 256>>>(enc, out_attn);

    // weight preprocessing
    split_kernel<<<(KIN*4*DU + 255)/256, 256>>>(Wx, pWx_h, pWx_l, KIN*4*DU);
    split_kernel<<<(DU*BV + 255)/256, 256>>>(Wfc, pWfc_h, pWfc_l, DU*BV);
    pack_wh_kernel<<<(128*512*16 + 255)/256, 256>>>(Wh);

    build_lstmin_split_kernel<<<(BT*KIN + 255)/256, 256>>>();

    // Z_in = lstm_in @ Wx + b_lstm   [2048,768]@[768,2048]
    gemm_mma3_kernel<<<dim3((4*DU)/128, BT/128), 256, GEMM_SMEM>>>(
        plin_h, plin_l, pWx_h, pWx_l, b_lstm, pzin, BT, 4*DU, KIN);

    lstm_kernel<<<128, 128, LSTM_SMEM>>>(h0, c0, out_h, out_c);

    // logits = hs @ Wfc + bfc   [2048,512]@[512,32000]
    gemm_mma3_kernel<<<dim3(BV/128, BT/128), 256, GEMM_SMEM>>>(
        phs_h, phs_l, pWfc_h, pWfc_l, bfc, out_logits, BT, BV, DU);
}